// round 8
// baseline (speedup 1.0000x reference)
#include <cuda_runtime.h>
#include <cstdint>
#include <cstddef>

// LocalConvolution via warp-level bf16 split MMA (mma.sync m16n8k16).
// Prep kernel pre-splits x into bf16 hi/lo transposed to [c,h,w][b].
// Main kernel: double-buffered smem, ONE sync per K-tile, W convert of tile
// t+1 interleaved into the MMA loop of tile t (issue-slot fusion).
// Per CTA (pos): D[o=128, b=64] = W[128,K] @ P[64,K]^T, K = 1600.

#define B_  64
#define C_  64
#define H_  32
#define W_  32
#define CC  28
#define O_  128
#define K_  1600
#define KT  64
#define NTILES 25
#define NPOS 784
#define CHW (C_*H_*W_)        // 65536

// per-buffer smem layout: bf16 tiles, 144B padded rows
#define ROWB 144
#define WHI_OFF 0
#define WLO_OFF (128*ROWB)                 // 18432
#define PHI_OFF (2*128*ROWB)               // 36864
#define PLO_OFF (2*128*ROWB + 64*ROWB)     // 46080
#define BUFSZ   (2*128*ROWB + 2*64*ROWB)   // 55296
#define SMEM_TOTAL (2*BUFSZ)               // 110592

__device__ uint4 g_xhi[CHW * B_ * 2 / 16];
__device__ uint4 g_xlo[CHW * B_ * 2 / 16];

__device__ __forceinline__ uint32_t smem_u32(const void* p) {
    uint32_t a;
    asm("{ .reg .u64 t; cvta.to.shared.u64 t, %1; cvt.u32.u64 %0, t; }" : "=r"(a) : "l"(p));
    return a;
}

__device__ __forceinline__ uint32_t cvt2(float flo, float fhi) {
    uint32_t r;
    asm("cvt.rn.bf16x2.f32 %0, %1, %2;" : "=r"(r) : "f"(fhi), "f"(flo));
    return r;
}

__device__ __forceinline__ void ldsm4(uint32_t* r, uint32_t addr) {
    asm volatile("ldmatrix.sync.aligned.m8n8.x4.shared.b16 {%0,%1,%2,%3}, [%4];"
                 : "=r"(r[0]), "=r"(r[1]), "=r"(r[2]), "=r"(r[3]) : "r"(addr));
}

__device__ __forceinline__ void ldsm4t(uint32_t* r, uint32_t addr) {
    asm volatile("ldmatrix.sync.aligned.m8n8.x4.trans.shared.b16 {%0,%1,%2,%3}, [%4];"
                 : "=r"(r[0]), "=r"(r[1]), "=r"(r[2]), "=r"(r[3]) : "r"(addr));
}

__device__ __forceinline__ void mma16816(float* d, const uint32_t* a, uint32_t b0, uint32_t b1) {
    asm volatile(
        "mma.sync.aligned.m16n8k16.row.col.f32.bf16.bf16.f32 "
        "{%0,%1,%2,%3}, {%4,%5,%6,%7}, {%8,%9}, {%0,%1,%2,%3};"
        : "+f"(d[0]), "+f"(d[1]), "+f"(d[2]), "+f"(d[3])
        : "r"(a[0]), "r"(a[1]), "r"(a[2]), "r"(a[3]), "r"(b0), "r"(b1));
}

// ---- prep: x[b][chw] f32 -> g_xhi/g_xlo [chw][b] bf16 (hi/lo RN split) ----
__global__ __launch_bounds__(256)
void prep_kernel(const float* __restrict__ x) {
    __shared__ float ts[B_][65];
    const int tid = threadIdx.x;
    const int wid = tid >> 5;
    const int lane = tid & 31;
    const int chw0 = blockIdx.x * 64;

    #pragma unroll
    for (int bi = 0; bi < 8; bi++) {
        int b = wid * 8 + bi;
        const float* xp = x + (size_t)b * CHW + chw0;
        ts[b][lane]      = xp[lane];
        ts[b][lane + 32] = xp[lane + 32];
    }
    __syncthreads();

    const int chw_l = tid >> 2;
    const int bc = tid & 3;
    uint32_t hi[8], lo[8];
    #pragma unroll
    for (int p = 0; p < 8; p++) {
        float f0 = ts[bc * 16 + p * 2][chw_l];
        float f1 = ts[bc * 16 + p * 2 + 1][chw_l];
        uint32_t h = cvt2(f0, f1);
        float l0 = f0 - __uint_as_float(h << 16);
        float l1 = f1 - __uint_as_float(h & 0xffff0000u);
        hi[p] = h;
        lo[p] = cvt2(l0, l1);
    }
    char* oh = (char*)g_xhi + (size_t)(chw0 + chw_l) * 128 + bc * 32;
    char* ol = (char*)g_xlo + (size_t)(chw0 + chw_l) * 128 + bc * 32;
    *(uint4*)oh        = make_uint4(hi[0], hi[1], hi[2], hi[3]);
    *(uint4*)(oh + 16) = make_uint4(hi[4], hi[5], hi[6], hi[7]);
    *(uint4*)ol        = make_uint4(lo[0], lo[1], lo[2], lo[3]);
    *(uint4*)(ol + 16) = make_uint4(lo[4], lo[5], lo[6], lo[7]);
}

// ---- main kernel ----
__global__ __launch_bounds__(256, 2)
void lc_hmma_kernel(const float* __restrict__ x,
                    const float* __restrict__ w,
                    float* __restrict__ out) {
    extern __shared__ char smem[];
    const uint32_t sbase = smem_u32(smem);

    const int tid = threadIdx.x;
    const int wid = tid >> 5;
    const int l   = tid & 31;

    const int pos = blockIdx.x;
    const int i = pos / CC;
    const int j = pos - i * CC;
    const float* __restrict__ wbase = w + (size_t)pos * (O_ * K_);

    const int o0 = (wid >> 1) * 32;
    const int b0 = (wid & 1) * 32;

    // P loader mapping: kr = tid>>2 (k row), c2 = tid&3 (32B chunk of b)
    const int kr = tid >> 2;
    const int c2 = tid & 3;

    // ldmatrix lane addresses (relative to buffer base)
    const uint32_t aRowRel = (uint32_t)((o0 + (l & 15)) * ROWB + (l >> 4) * 16);
    const uint32_t bRowRel = (uint32_t)(PHI_OFF + (((l >> 3) & 1) * 8 + (l & 7)) * ROWB
                                        + (b0 + (l >> 4) * 8) * 2);

    float acc[2][4][4];
    #pragma unroll
    for (int mi = 0; mi < 2; mi++)
        #pragma unroll
        for (int bt = 0; bt < 4; bt++)
            #pragma unroll
            for (int c = 0; c < 4; c++) acc[mi][bt][c] = 0.0f;

    float4 wreg[8];
    auto load_w = [&](int t) {
        const float* wt = wbase + t * KT;
        #pragma unroll
        for (int ci = 0; ci < 8; ci++) {
            int ch = tid + ci * 256;
            int o = ch >> 4, kc = ch & 15;
            wreg[ci] = *(const float4*)(wt + (size_t)o * K_ + kc * 4);
        }
    };

    // convert one W chunk ci from wreg into buffer at bufOff
    auto cvt_chunk = [&](int ci, uint32_t bufOff) {
        int ch = tid + ci * 256;
        int o = ch >> 4, kc = ch & 15;
        float4 f = wreg[ci];
        uint32_t h01 = cvt2(f.x, f.y);
        uint32_t h23 = cvt2(f.z, f.w);
        float lo0 = f.x - __uint_as_float(h01 << 16);
        float lo1 = f.y - __uint_as_float(h01 & 0xffff0000u);
        float lo2 = f.z - __uint_as_float(h23 << 16);
        float lo3 = f.w - __uint_as_float(h23 & 0xffff0000u);
        uint32_t l01 = cvt2(lo0, lo1);
        uint32_t l23 = cvt2(lo2, lo3);
        uint32_t off = bufOff + (uint32_t)o * ROWB + (uint32_t)kc * 8;
        *(uint2*)(smem + WHI_OFF + off) = make_uint2(h01, h23);
        *(uint2*)(smem + WLO_OFF + off) = make_uint2(l01, l23);
    };

    // P source address for tile t (this thread's row)
    auto p_src = [&](int t) -> size_t {
        int kg = t * KT + kr;
        int c = kg / 25;
        int rem = kg - c * 25;
        int u = rem / 5;
        int v = rem - u * 5;
        return ((size_t)(c * (H_ * W_) + (i + u) * W_ + (j + v))) * 128 + c2 * 32;
    };

    // MMA block on buffer bufOff; optionally interleave W convert to cvtOff
    auto mma_tile = [&](uint32_t bufOff, uint32_t cvtOff, bool doCvt) {
        const uint32_t aRow = sbase + bufOff + aRowRel;
        const uint32_t bRow = sbase + bufOff + bRowRel;
        #pragma unroll
        for (int ks = 0; ks < 4; ks++) {
            const uint32_t aCol = (uint32_t)ks * 32;
            const uint32_t bOff = (uint32_t)ks * 16 * ROWB;
            uint32_t ah[2][4], al[2][4];
            ldsm4(ah[0], aRow + aCol);
            ldsm4(ah[1], aRow + aCol + 16 * ROWB);
            ldsm4(al[0], aRow + aCol + (WLO_OFF - WHI_OFF));
            ldsm4(al[1], aRow + aCol + (WLO_OFF - WHI_OFF) + 16 * ROWB);
            #pragma unroll
            for (int g = 0; g < 2; g++) {
                uint32_t bh[4], bl[4];
                ldsm4t(bh, bRow + bOff + g * 32);
                ldsm4t(bl, bRow + bOff + (PLO_OFF - PHI_OFF) + g * 32);
                #pragma unroll
                for (int mi = 0; mi < 2; mi++) {
                    #pragma unroll
                    for (int p = 0; p < 2; p++) {
                        float* d = acc[mi][g * 2 + p];
                        mma16816(d, ah[mi], bh[p * 2], bh[p * 2 + 1]);
                        mma16816(d, ah[mi], bl[p * 2], bl[p * 2 + 1]);
                        mma16816(d, al[mi], bh[p * 2], bh[p * 2 + 1]);
                    }
                }
            }
            if (doCvt) {            // 2 of 8 W chunks per ks-step
                cvt_chunk(2 * ks, cvtOff);
                cvt_chunk(2 * ks + 1, cvtOff);
            }
        }
    };

    // ---- prologue: tile0 -> buf0, wreg <- tile1 ----
    {
        load_w(0);
        size_t sp = p_src(0);
        uint4 ph0 = *(const uint4*)((const char*)g_xhi + sp);
        uint4 ph1 = *(const uint4*)((const char*)g_xhi + sp + 16);
        uint4 pl0 = *(const uint4*)((const char*)g_xlo + sp);
        uint4 pl1 = *(const uint4*)((const char*)g_xlo + sp + 16);
        #pragma unroll
        for (int ci = 0; ci < 8; ci++) cvt_chunk(ci, 0);
        char* dh = smem + PHI_OFF + kr * ROWB + c2 * 32;
        char* dl = smem + PLO_OFF + kr * ROWB + c2 * 32;
        *(uint4*)dh = ph0; *(uint4*)(dh + 16) = ph1;
        *(uint4*)dl = pl0; *(uint4*)(dl + 16) = pl1;
        load_w(1);
        __syncthreads();
    }

    // ---- main loop: tiles 0..23 full pipeline ----
    #pragma unroll 1
    for (int t = 0; t < NTILES - 1; t++) {
        const uint32_t bufOff  = (uint32_t)(t & 1) * BUFSZ;
        const uint32_t bufOffN = BUFSZ - bufOff;

        // P(t+1) loads issued now, consumed after the MMA loop
        size_t sp = p_src(t + 1);
        uint4 ph0 = *(const uint4*)((const char*)g_xhi + sp);
        uint4 ph1 = *(const uint4*)((const char*)g_xhi + sp + 16);
        uint4 pl0 = *(const uint4*)((const char*)g_xlo + sp);
        uint4 pl1 = *(const uint4*)((const char*)g_xlo + sp + 16);

        // MMA(t) with W(t+1) convert interleaved into buf^1
        mma_tile(bufOff, bufOffN, true);

        // P(t+1) STS
        char* dh = smem + PHI_OFF + bufOffN + kr * ROWB + c2 * 32;
        char* dl = smem + PLO_OFF + bufOffN + kr * ROWB + c2 * 32;
        *(uint4*)dh = ph0; *(uint4*)(dh + 16) = ph1;
        *(uint4*)dl = pl0; *(uint4*)(dl + 16) = pl1;

        // W(t+2) prefetch (guarded; redundant reload on last two iters)
        int tn = (t + 2 < NTILES) ? (t + 2) : (NTILES - 1);
        load_w(tn);

        __syncthreads();
    }

    // ---- peeled last tile: MMA only ----
    mma_tile((uint32_t)((NTILES - 1) & 1) * BUFSZ, 0, false);

    // ---- epilogue ----
    const int orow = l >> 2;
    const int bcol = (l & 3) * 2;
    #pragma unroll
    for (int mi = 0; mi < 2; mi++) {
        #pragma unroll
        for (int bt = 0; bt < 4; bt++) {
            #pragma unroll
            for (int c = 0; c < 4; c++) {
                int o = o0 + mi * 16 + orow + (c >> 1) * 8;
                int b = b0 + bt * 8 + bcol + (c & 1);
                out[((size_t)b * O_ + o) * NPOS + pos] = acc[mi][bt][c];
            }
        }
    }
}

extern "C" void kernel_launch(void* const* d_in, const int* in_sizes, int n_in,
                              void* d_out, int out_size) {
    const float* x;
    const float* w;
    if (in_sizes[0] == B_ * C_ * H_ * W_) {
        x = (const float*)d_in[0];
        w = (const float*)d_in[1];
    } else {
        x = (const float*)d_in[1];
        w = (const float*)d_in[0];
    }
    float* out = (float*)d_out;
    prep_kernel<<<CHW / 64, 256>>>(x);
    cudaFuncSetAttribute(lc_hmma_kernel, cudaFuncAttributeMaxDynamicSharedMemorySize, SMEM_TOTAL);
    lc_hmma_kernel<<<NPOS, 256, SMEM_TOTAL>>>(x, w, out);
}